// round 5
// baseline (speedup 1.0000x reference)
#include <cuda_runtime.h>

#define B_SZ 16
#define LM   1024
#define LX   1024
#define D    768
#define NSPLIT 32

// Scratch (static device arrays; allocation-free per harness rules)
__device__ float g_G[B_SZ * D * D];        // x^T x per batch           (36 MB)
__device__ float g_Mm[B_SZ * D * D];       // W @ G per batch           (36 MB)
__device__ float g_A[B_SZ * LM * D];       // attended features         (48 MB)
__device__ float g_beta[B_SZ * LM];
__device__ float g_part[B_SZ * NSPLIT * 2 * D];

// ---------------------------------------------------------------------------
// NN SGEMM: C[M,N] = A[M,K] @ B[K,N]  (all row-major). 128x128x8 tile,
// 256 threads, 8x8 per thread. Dims must be multiples of 128/8 (they are).
// ---------------------------------------------------------------------------
__global__ __launch_bounds__(256) void sgemm_nn(
    const float* __restrict__ Ag, const float* __restrict__ Bg,
    float* __restrict__ Cg, int M, int N, int K,
    size_t sA, size_t sB, size_t sC)
{
    __shared__ float As[8][132];   // padded to kill STS conflicts on transpose store
    __shared__ float Bs[8][128];

    const float* A  = Ag + (size_t)blockIdx.z * sA;
    const float* Bp = Bg + (size_t)blockIdx.z * sB;
    float*       C  = Cg + (size_t)blockIdx.z * sC;

    const int brow = blockIdx.y * 128;
    const int bcol = blockIdx.x * 128;
    const int tid  = threadIdx.x;
    const int tx   = tid & 15;
    const int ty   = tid >> 4;

    const int aRow = tid >> 1;          // 128 rows, 2 threads/row
    const int aCol = (tid & 1) * 4;     // each thread: float4 along K
    const int bRow = tid >> 5;          // 8 rows, 32 threads/row
    const int bCol = (tid & 31) * 4;

    float acc[8][8];
#pragma unroll
    for (int i = 0; i < 8; i++)
#pragma unroll
        for (int j = 0; j < 8; j++) acc[i][j] = 0.f;

    for (int k0 = 0; k0 < K; k0 += 8) {
        float4 av = *(const float4*)&A[(size_t)(brow + aRow) * K + k0 + aCol];
        As[aCol + 0][aRow] = av.x;
        As[aCol + 1][aRow] = av.y;
        As[aCol + 2][aRow] = av.z;
        As[aCol + 3][aRow] = av.w;
        *(float4*)&Bs[bRow][bCol] =
            *(const float4*)&Bp[(size_t)(k0 + bRow) * N + bcol + bCol];
        __syncthreads();

#pragma unroll
        for (int kk = 0; kk < 8; kk++) {
            float4 a0 = *(const float4*)&As[kk][ty * 8];
            float4 a1 = *(const float4*)&As[kk][ty * 8 + 4];
            float4 b0 = *(const float4*)&Bs[kk][tx * 8];
            float4 b1 = *(const float4*)&Bs[kk][tx * 8 + 4];
            float ar[8] = {a0.x, a0.y, a0.z, a0.w, a1.x, a1.y, a1.z, a1.w};
            float br[8] = {b0.x, b0.y, b0.z, b0.w, b1.x, b1.y, b1.z, b1.w};
#pragma unroll
            for (int i = 0; i < 8; i++)
#pragma unroll
                for (int j = 0; j < 8; j++) acc[i][j] += ar[i] * br[j];
        }
        __syncthreads();
    }

#pragma unroll
    for (int i = 0; i < 8; i++) {
        const size_t r = (size_t)(brow + ty * 8 + i) * N + bcol + tx * 8;
        *(float4*)&C[r]     = make_float4(acc[i][0], acc[i][1], acc[i][2], acc[i][3]);
        *(float4*)&C[r + 4] = make_float4(acc[i][4], acc[i][5], acc[i][6], acc[i][7]);
    }
}

// ---------------------------------------------------------------------------
// TN SGEMM: C[M,N] = A^T @ B, A: KxM row-major, B: KxN row-major.
// Tiles load directly as [BK][BM]/[BK][BN] — fully coalesced, no transpose.
// ---------------------------------------------------------------------------
__global__ __launch_bounds__(256) void sgemm_tn(
    const float* __restrict__ Ag, const float* __restrict__ Bg,
    float* __restrict__ Cg, int M, int N, int K,
    size_t sA, size_t sB, size_t sC)
{
    __shared__ float As[8][128];
    __shared__ float Bs[8][128];

    const float* A  = Ag + (size_t)blockIdx.z * sA;
    const float* Bp = Bg + (size_t)blockIdx.z * sB;
    float*       C  = Cg + (size_t)blockIdx.z * sC;

    const int brow = blockIdx.y * 128;
    const int bcol = blockIdx.x * 128;
    const int tid  = threadIdx.x;
    const int tx   = tid & 15;
    const int ty   = tid >> 4;

    const int lRow = tid >> 5;          // 8 rows
    const int lCol = (tid & 31) * 4;    // 128 cols via float4

    float acc[8][8];
#pragma unroll
    for (int i = 0; i < 8; i++)
#pragma unroll
        for (int j = 0; j < 8; j++) acc[i][j] = 0.f;

    for (int k0 = 0; k0 < K; k0 += 8) {
        *(float4*)&As[lRow][lCol] =
            *(const float4*)&A[(size_t)(k0 + lRow) * M + brow + lCol];
        *(float4*)&Bs[lRow][lCol] =
            *(const float4*)&Bp[(size_t)(k0 + lRow) * N + bcol + lCol];
        __syncthreads();

#pragma unroll
        for (int kk = 0; kk < 8; kk++) {
            float4 a0 = *(const float4*)&As[kk][ty * 8];
            float4 a1 = *(const float4*)&As[kk][ty * 8 + 4];
            float4 b0 = *(const float4*)&Bs[kk][tx * 8];
            float4 b1 = *(const float4*)&Bs[kk][tx * 8 + 4];
            float ar[8] = {a0.x, a0.y, a0.z, a0.w, a1.x, a1.y, a1.z, a1.w};
            float br[8] = {b0.x, b0.y, b0.z, b0.w, b1.x, b1.y, b1.z, b1.w};
#pragma unroll
            for (int i = 0; i < 8; i++)
#pragma unroll
                for (int j = 0; j < 8; j++) acc[i][j] += ar[i] * br[j];
        }
        __syncthreads();
    }

#pragma unroll
    for (int i = 0; i < 8; i++) {
        const size_t r = (size_t)(brow + ty * 8 + i) * N + bcol + tx * 8;
        *(float4*)&C[r]     = make_float4(acc[i][0], acc[i][1], acc[i][2], acc[i][3]);
        *(float4*)&C[r + 4] = make_float4(acc[i][4], acc[i][5], acc[i][6], acc[i][7]);
    }
}

// ---------------------------------------------------------------------------
// beta[b,m] = sum_d (main-A)*w1 + (main*A)*w2 ; one block per (b,m) row
// ---------------------------------------------------------------------------
__global__ __launch_bounds__(256) void beta_kernel(
    const float* __restrict__ mainp, const float* __restrict__ w)
{
    const int bm = blockIdx.x;
    const float* mp = mainp + (size_t)bm * D;
    const float* ap = g_A   + (size_t)bm * D;

    float sum = 0.f;
    for (int d = threadIdx.x; d < D; d += 256) {
        float mv = mp[d], av = ap[d];
        sum += (mv - av) * w[d] + (mv * av) * w[D + d];
    }
#pragma unroll
    for (int o = 16; o; o >>= 1) sum += __shfl_xor_sync(0xffffffffu, sum, o);

    __shared__ float red[8];
    if ((threadIdx.x & 31) == 0) red[threadIdx.x >> 5] = sum;
    __syncthreads();
    if (threadIdx.x < 8) {
        float v = red[threadIdx.x];
#pragma unroll
        for (int o = 4; o; o >>= 1) v += __shfl_xor_sync(0xffu, v, o);
        if (threadIdx.x == 0) g_beta[bm] = v;
    }
}

// ---------------------------------------------------------------------------
// Partial pooled sums: split LM into NSPLIT chunks (deterministic, no atomics)
// ---------------------------------------------------------------------------
__global__ __launch_bounds__(768) void pooled_partial(const float* __restrict__ mainp)
{
    const int b  = blockIdx.y;
    const int sp = blockIdx.x;
    const int d  = threadIdx.x;            // 0..D-1
    const int m0 = sp * (LM / NSPLIT);

    const float* mp = mainp  + ((size_t)b * LM + m0) * D + d;
    const float* ap = g_A    + ((size_t)b * LM + m0) * D + d;
    const float* bp = g_beta + (size_t)b * LM + m0;

    float ss = 0.f, sm = 0.f;
#pragma unroll 4
    for (int i = 0; i < LM / NSPLIT; i++) {
        float bt = bp[i];
        float mv = mp[(size_t)i * D];
        float av = ap[(size_t)i * D];
        ss += bt * (mv - av);
        sm += bt * (mv * av);
    }
    float* pp = g_part + (size_t)(b * NSPLIT + sp) * 2 * D;
    pp[d]     = ss;
    pp[D + d] = sm;
}

__global__ __launch_bounds__(256) void pooled_reduce(float* __restrict__ out)
{
    const int b = blockIdx.x;
    for (int k = threadIdx.x; k < 2 * D; k += 256) {
        float s = 0.f;
#pragma unroll
        for (int sp = 0; sp < NSPLIT; sp++)
            s += g_part[(size_t)(b * NSPLIT + sp) * 2 * D + k];
        out[(size_t)b * 2 * D + k] = s;
    }
}

// ---------------------------------------------------------------------------
extern "C" void kernel_launch(void* const* d_in, const int* in_sizes, int n_in,
                              void* d_out, int out_size)
{
    const float* mainp = (const float*)d_in[0];   // (B, LM, D)
    const float* xp    = (const float*)d_in[1];   // (B, LX, D)
    const float* Wp    = (const float*)d_in[2];   // (D, D)
    const float* wp    = (const float*)d_in[3];   // (2D, 1)
    float*       out   = (float*)d_out;           // (B, 2D)

    float *G, *Mm, *Aout;
    cudaGetSymbolAddress((void**)&G,    g_G);
    cudaGetSymbolAddress((void**)&Mm,   g_Mm);
    cudaGetSymbolAddress((void**)&Aout, g_A);

    // 1) G_b = x_b^T @ x_b           (D x D, K = LX)
    sgemm_tn<<<dim3(D / 128, D / 128, B_SZ), 256>>>(
        xp, xp, G, D, D, LX, (size_t)LX * D, (size_t)LX * D, (size_t)D * D);

    // 2) M_b = W @ G_b               (D x D, K = D); W shared across batch
    sgemm_nn<<<dim3(D / 128, D / 128, B_SZ), 256>>>(
        Wp, G, Mm, D, D, D, 0, (size_t)D * D, (size_t)D * D);

    // 3) A_b = main_b @ M_b          (LM x D, K = D)
    sgemm_nn<<<dim3(D / 128, LM / 128, B_SZ), 256>>>(
        mainp, Mm, Aout, LM, D, D, (size_t)LM * D, (size_t)D * D, (size_t)LM * D);

    // 4) beta
    beta_kernel<<<B_SZ * LM, 256>>>(mainp, wp);

    // 5) pooled (split + deterministic reduce)
    pooled_partial<<<dim3(NSPLIT, B_SZ), 768>>>(mainp);
    pooled_reduce<<<B_SZ, 256>>>(out);
}

// round 7
// speedup vs baseline: 2.6622x; 2.6622x over previous
#include <cuda_runtime.h>
#include <cuda_bf16.h>
#include <cstdint>

#define B_SZ 16
#define LM   1024
#define LX   1024
#define D    768
#define NSPLIT 32

// ---------------- scratch (static; allocation-free) ----------------
__device__ unsigned short g_xTh[(size_t)B_SZ * D * LX];
__device__ unsigned short g_xTl[(size_t)B_SZ * D * LX];
__device__ unsigned short g_Gh [(size_t)B_SZ * D * D];
__device__ unsigned short g_Gl [(size_t)B_SZ * D * D];
__device__ unsigned short g_Ph [(size_t)B_SZ * D * D];
__device__ unsigned short g_Pl [(size_t)B_SZ * D * D];
__device__ unsigned short g_mh [(size_t)B_SZ * LM * D];
__device__ unsigned short g_ml [(size_t)B_SZ * LM * D];
__device__ unsigned short g_Wh [D * D];
__device__ unsigned short g_Wl [D * D];
__device__ float g_A   [(size_t)B_SZ * LM * D];
__device__ float g_beta[B_SZ * LM];
__device__ float g_part[B_SZ * NSPLIT * 2 * D];

// ---------------- helpers ----------------
__device__ __forceinline__ uint32_t smem_u32(const void* p) {
    uint32_t a;
    asm("{ .reg .u64 t; cvta.to.shared.u64 t, %1; cvt.u32.u64 %0, t; }" : "=r"(a) : "l"(p));
    return a;
}
__device__ __forceinline__ void cpa16(uint32_t dst, const void* src) {
    asm volatile("cp.async.cg.shared.global [%0], [%1], 16;" :: "r"(dst), "l"(src));
}
#define CP_COMMIT() asm volatile("cp.async.commit_group;" ::: "memory")
#define CP_WAIT(n)  asm volatile("cp.async.wait_group %0;" :: "n"(n) : "memory")

__device__ __forceinline__ void ldm4(uint32_t* r, uint32_t addr) {
    asm volatile("ldmatrix.sync.aligned.m8n8.x4.shared.b16 {%0,%1,%2,%3}, [%4];"
                 : "=r"(r[0]), "=r"(r[1]), "=r"(r[2]), "=r"(r[3]) : "r"(addr));
}
__device__ __forceinline__ void mma16816(float* d, const uint32_t* a, uint32_t b0, uint32_t b1) {
    asm volatile("mma.sync.aligned.m16n8k16.row.col.f32.bf16.bf16.f32 "
                 "{%0,%1,%2,%3}, {%4,%5,%6,%7}, {%8,%9}, {%0,%1,%2,%3};"
                 : "+f"(d[0]), "+f"(d[1]), "+f"(d[2]), "+f"(d[3])
                 : "r"(a[0]), "r"(a[1]), "r"(a[2]), "r"(a[3]), "r"(b0), "r"(b1));
}
__device__ __forceinline__ void split1(float v, unsigned short& h, unsigned short& l) {
    __nv_bfloat16 hb = __float2bfloat16(v);
    __nv_bfloat16 lb = __float2bfloat16(v - __bfloat162float(hb));
    h = __bfloat16_as_ushort(hb);
    l = __bfloat16_as_ushort(lb);
}
__device__ __forceinline__ uint32_t packus(unsigned short a, unsigned short b) {
    return ((uint32_t)b << 16) | (uint32_t)a;
}

// ---------------------------------------------------------------------------
// bf16 split-GEMM: C[M,N] = A*B^T where A = Ah+Al, B = Bh+Bl (bf16 hi/lo),
// fp32 accumulate via mma.sync m16n8k16. A: [M,K], B: [N,K], bf16 row-major.
// CTA 128x128, K-chunk 64, cp.async 2-stage pipeline, swizzled smem.
// ---------------------------------------------------------------------------
#define TILE_B 16384                 // 128 x 64 bf16
#define STAGE_B (4 * TILE_B)
#define GSMEM   (2 * STAGE_B)        // 128 KB

__global__ __launch_bounds__(256, 1) void gemm_bf16(
    const unsigned short* __restrict__ Ah, const unsigned short* __restrict__ Al,
    const unsigned short* __restrict__ Bh, const unsigned short* __restrict__ Bl,
    float* __restrict__ C, unsigned short* __restrict__ Ch, unsigned short* __restrict__ Cl,
    int N, int K, long sA, long sB, long sC, int split_out)
{
    extern __shared__ char smem[];
    const uint32_t sbt = smem_u32(smem);

    const int tid  = threadIdx.x;
    const int lane = tid & 31;
    const int wid  = tid >> 5;
    const int warp_m = wid & 1;        // 2 warps along M (64 rows each)
    const int warp_n = wid >> 1;       // 4 warps along N (32 cols each)
    const int brow = blockIdx.y * 128, bcol = blockIdx.x * 128;
    const long bz = blockIdx.z;

    // loader assignment: tile g (Ah,Al,Bh,Bl), 64 threads/tile
    const int g  = tid >> 6;
    const int s  = tid & 63;
    const int rb = s >> 3;             // base row 0..7
    const int u  = s & 7;              // 16B-unit within 128B row
    const unsigned short* src;
    {
        const unsigned short* s0 = Ah + bz * sA + (size_t)brow * K;
        const unsigned short* s1 = Al + bz * sA + (size_t)brow * K;
        const unsigned short* s2 = Bh + bz * sB + (size_t)bcol * K;
        const unsigned short* s3 = Bl + bz * sB + (size_t)bcol * K;
        src = (g == 0) ? s0 : (g == 1) ? s1 : (g == 2) ? s2 : s3;
    }

    const int NC = K >> 6;

    auto issue = [&](int c) {
        const uint32_t st = sbt + (c & 1) * STAGE_B + g * TILE_B;
        const unsigned short* sp = src + c * 64 + u * 8;
#pragma unroll
        for (int i = 0; i < 16; i++) {
            int r = rb + 8 * i;
            cpa16(st + (uint32_t)((r * 8 + (u ^ (r & 7))) * 16), sp + (size_t)r * K);
        }
    };

    float acc[4][4][4];
#pragma unroll
    for (int a = 0; a < 4; a++)
#pragma unroll
        for (int b = 0; b < 4; b++)
#pragma unroll
            for (int q = 0; q < 4; q++) acc[a][b][q] = 0.f;

    const int a_r    = lane & 15;
    const int a_kbit = lane >> 4;
    const int b_r    = (lane & 7) + ((lane >> 4) << 3);
    const int b_kbit = (lane >> 3) & 1;

    issue(0); CP_COMMIT();

    for (int c = 0; c < NC; c++) {
        if (c + 1 < NC) { issue(c + 1); CP_COMMIT(); CP_WAIT(1); }
        else            { CP_WAIT(0); }
        __syncthreads();

        const uint32_t stg = sbt + (c & 1) * STAGE_B;
#pragma unroll
        for (int kk = 0; kk < 4; kk++) {
            uint32_t ah[4][4], al[4][4], bh[2][4], bl[2][4];
#pragma unroll
            for (int mt = 0; mt < 4; mt++) {
                int row = warp_m * 64 + mt * 16 + a_r;
                int ku  = kk * 2 + a_kbit;
                uint32_t off = (uint32_t)((row * 8 + (ku ^ (row & 7))) * 16);
                ldm4(ah[mt], stg + off);
                ldm4(al[mt], stg + TILE_B + off);
            }
#pragma unroll
            for (int p = 0; p < 2; p++) {
                int row = warp_n * 32 + p * 16 + b_r;
                int ku  = kk * 2 + b_kbit;
                uint32_t off = (uint32_t)((row * 8 + (ku ^ (row & 7))) * 16);
                ldm4(bh[p], stg + 2 * TILE_B + off);
                ldm4(bl[p], stg + 3 * TILE_B + off);
            }
#pragma unroll
            for (int mt = 0; mt < 4; mt++)
#pragma unroll
                for (int nt = 0; nt < 4; nt++) {
                    const int p = nt >> 1, q = (nt & 1) * 2;
                    mma16816(acc[mt][nt], ah[mt], bh[p][q], bh[p][q + 1]);
                    mma16816(acc[mt][nt], al[mt], bh[p][q], bh[p][q + 1]);
                    mma16816(acc[mt][nt], ah[mt], bl[p][q], bl[p][q + 1]);
                }
        }
        __syncthreads();
    }

    // epilogue
    float*          Cb  = C  ? C  + bz * sC : nullptr;
    unsigned short* Chb = Ch + bz * sC;
    unsigned short* Clb = Cl + bz * sC;
#pragma unroll
    for (int mt = 0; mt < 4; mt++)
#pragma unroll
        for (int nt = 0; nt < 4; nt++) {
            const float* dd = acc[mt][nt];
            const int r   = brow + warp_m * 64 + mt * 16 + (lane >> 2);
            const int col = bcol + warp_n * 32 + nt * 8 + (lane & 3) * 2;
            if (!split_out) {
                *(float2*)&Cb[(size_t)r * N + col]       = make_float2(dd[0], dd[1]);
                *(float2*)&Cb[(size_t)(r + 8) * N + col] = make_float2(dd[2], dd[3]);
            } else {
                unsigned short h0, l0, h1, l1;
                split1(dd[0], h0, l0); split1(dd[1], h1, l1);
                *(uint32_t*)&Chb[(size_t)r * N + col] = packus(h0, h1);
                *(uint32_t*)&Clb[(size_t)r * N + col] = packus(l0, l1);
                split1(dd[2], h0, l0); split1(dd[3], h1, l1);
                *(uint32_t*)&Chb[(size_t)(r + 8) * N + col] = packus(h0, h1);
                *(uint32_t*)&Clb[(size_t)(r + 8) * N + col] = packus(l0, l1);
            }
        }
}

// ---------------------------------------------------------------------------
// x [B,LX,D] fp32 -> xTh/xTl [B,D,LX] bf16 hi/lo (fused transpose + split)
// ---------------------------------------------------------------------------
__global__ __launch_bounds__(256) void transpose_split_x(const float* __restrict__ x)
{
    __shared__ float t[32][33];
    const int b = blockIdx.z;
    const int l0 = blockIdx.x * 32, d0 = blockIdx.y * 32;
    const int tx = threadIdx.x, ty = threadIdx.y;
    const float* xp = x + (size_t)b * LX * D;
#pragma unroll
    for (int i = 0; i < 32; i += 8)
        t[ty + i][tx] = xp[(size_t)(l0 + ty + i) * D + d0 + tx];
    __syncthreads();
#pragma unroll
    for (int i = 0; i < 32; i += 8) {
        float v = t[tx][ty + i];
        unsigned short h, l; split1(v, h, l);
        size_t o = ((size_t)b * D + d0 + ty + i) * LX + l0 + tx;
        g_xTh[o] = h;
        g_xTl[o] = l;
    }
}

// fp32 -> bf16 hi/lo split (vectorized, n must be multiple of 4)
__global__ __launch_bounds__(256) void split_kernel(
    const float* __restrict__ src, unsigned short* __restrict__ h,
    unsigned short* __restrict__ l, int n4)
{
    int i = blockIdx.x * 256 + threadIdx.x;
    if (i >= n4) return;
    float4 v = ((const float4*)src)[i];
    unsigned short h0, l0, h1, l1, h2, l2, h3, l3;
    split1(v.x, h0, l0); split1(v.y, h1, l1);
    split1(v.z, h2, l2); split1(v.w, h3, l3);
    ((uint2*)h)[i] = make_uint2(packus(h0, h1), packus(h2, h3));
    ((uint2*)l)[i] = make_uint2(packus(l0, l1), packus(l2, l3));
}

// ---------------------------------------------------------------------------
// beta[b,m] = sum_d (main-A)*w1 + (main*A)*w2
// ---------------------------------------------------------------------------
__global__ __launch_bounds__(256) void beta_kernel(
    const float* __restrict__ mainp, const float* __restrict__ w)
{
    const int bm = blockIdx.x;
    const float* mp = mainp + (size_t)bm * D;
    const float* ap = g_A   + (size_t)bm * D;

    float sum = 0.f;
    for (int d = threadIdx.x; d < D; d += 256) {
        float mv = mp[d], av = ap[d];
        sum += (mv - av) * w[d] + (mv * av) * w[D + d];
    }
#pragma unroll
    for (int o = 16; o; o >>= 1) sum += __shfl_xor_sync(0xffffffffu, sum, o);

    __shared__ float red[8];
    if ((threadIdx.x & 31) == 0) red[threadIdx.x >> 5] = sum;
    __syncthreads();
    if (threadIdx.x < 8) {
        float v = red[threadIdx.x];
#pragma unroll
        for (int o = 4; o; o >>= 1) v += __shfl_xor_sync(0xffu, v, o);
        if (threadIdx.x == 0) g_beta[bm] = v;
    }
}

__global__ __launch_bounds__(768) void pooled_partial(const float* __restrict__ mainp)
{
    const int b  = blockIdx.y;
    const int sp = blockIdx.x;
    const int d  = threadIdx.x;
    const int m0 = sp * (LM / NSPLIT);

    const float* mp = mainp  + ((size_t)b * LM + m0) * D + d;
    const float* ap = g_A    + ((size_t)b * LM + m0) * D + d;
    const float* bp = g_beta + (size_t)b * LM + m0;

    float ss = 0.f, sm = 0.f;
#pragma unroll 4
    for (int i = 0; i < LM / NSPLIT; i++) {
        float bt = bp[i];
        float mv = mp[(size_t)i * D];
        float av = ap[(size_t)i * D];
        ss += bt * (mv - av);
        sm += bt * (mv * av);
    }
    float* pp = g_part + (size_t)(b * NSPLIT + sp) * 2 * D;
    pp[d]     = ss;
    pp[D + d] = sm;
}

__global__ __launch_bounds__(256) void pooled_reduce(float* __restrict__ out)
{
    const int b = blockIdx.x;
    for (int k = threadIdx.x; k < 2 * D; k += 256) {
        float s = 0.f;
#pragma unroll
        for (int sp = 0; sp < NSPLIT; sp++)
            s += g_part[(size_t)(b * NSPLIT + sp) * 2 * D + k];
        out[(size_t)b * 2 * D + k] = s;
    }
}

// ---------------------------------------------------------------------------
extern "C" void kernel_launch(void* const* d_in, const int* in_sizes, int n_in,
                              void* d_out, int out_size)
{
    const float* mainp = (const float*)d_in[0];   // (B, LM, D)
    const float* xp    = (const float*)d_in[1];   // (B, LX, D)
    const float* Wp    = (const float*)d_in[2];   // (D, D)
    const float* wp    = (const float*)d_in[3];   // (2D, 1)
    float*       out   = (float*)d_out;           // (B, 2D)

    cudaFuncSetAttribute(gemm_bf16, cudaFuncAttributeMaxDynamicSharedMemorySize, GSMEM);

    unsigned short *xTh, *xTl, *Gh, *Gl, *Ph, *Pl, *mh, *ml, *Wh, *Wl;
    float *Aout;
    cudaGetSymbolAddress((void**)&xTh, g_xTh);
    cudaGetSymbolAddress((void**)&xTl, g_xTl);
    cudaGetSymbolAddress((void**)&Gh,  g_Gh);
    cudaGetSymbolAddress((void**)&Gl,  g_Gl);
    cudaGetSymbolAddress((void**)&Ph,  g_Ph);
    cudaGetSymbolAddress((void**)&Pl,  g_Pl);
    cudaGetSymbolAddress((void**)&mh,  g_mh);
    cudaGetSymbolAddress((void**)&ml,  g_ml);
    cudaGetSymbolAddress((void**)&Wh,  g_Wh);
    cudaGetSymbolAddress((void**)&Wl,  g_Wl);
    cudaGetSymbolAddress((void**)&Aout, g_A);

    // operand preparation (bf16 hi/lo)
    transpose_split_x<<<dim3(LX / 32, D / 32, B_SZ), dim3(32, 8)>>>(xp);
    split_kernel<<<(D * D / 4 + 255) / 256, 256>>>(Wp, Wh, Wl, D * D / 4);
    split_kernel<<<((int)((size_t)B_SZ * LM * D / 4) + 255) / 256, 256>>>(
        mainp, mh, ml, (int)((size_t)B_SZ * LM * D / 4));

    // 1) G_b = xT_b @ xT_b^T   (D x D, K = LX), split-bf16 output
    gemm_bf16<<<dim3(D / 128, D / 128, B_SZ), 256, GSMEM>>>(
        xTh, xTl, xTh, xTl, nullptr, Gh, Gl,
        D, LX, (long)D * LX, (long)D * LX, (long)D * D, 1);

    // 2) P_b = G_b @ W^T       (D x D, K = D), W broadcast, split output
    gemm_bf16<<<dim3(D / 128, D / 128, B_SZ), 256, GSMEM>>>(
        Gh, Gl, Wh, Wl, nullptr, Ph, Pl,
        D, D, (long)D * D, 0L, (long)D * D, 1);

    // 3) A_b = main_b @ P_b^T  (LM x D, K = D), fp32 output
    gemm_bf16<<<dim3(D / 128, LM / 128, B_SZ), 256, GSMEM>>>(
        mh, ml, Ph, Pl, Aout, Ph, Pl,
        D, D, (long)LM * D, (long)D * D, (long)LM * D, 0);

    // 4) beta
    beta_kernel<<<B_SZ * LM, 256>>>(mainp, wp);

    // 5) pooled (split + deterministic reduce)
    pooled_partial<<<dim3(NSPLIT, B_SZ), 768>>>(mainp);
    pooled_reduce<<<B_SZ, 256>>>(out);
}